// round 6
// baseline (speedup 1.0000x reference)
#include <cuda_runtime.h>
#include <cstdint>

#define A_N 100000
#define B_N 200000
#define NBN 6
#define FA 133
#define FB 147
#define H 256
#define M_N 5000
#define DEPTH 4

// ---------------- device scratch (no allocations allowed) ----------------
__device__ float g_input_atom[(size_t)A_N * H];
__device__ float g_input_bond[(size_t)B_N * H];
__device__ float g_message_atom[(size_t)A_N * H];
__device__ float g_mb0[(size_t)B_N * H];
__device__ float g_mb1[(size_t)B_N * H];
__device__ float g_agg[(size_t)A_N * H];
__device__ float g_h1[(size_t)A_N * H];
__device__ float g_ah[(size_t)A_N * H];
__device__ int   g_offsets[M_N];

// pre-formatted B weights: per region (ny, kb16) 4096 floats, fragment layout,
// element idx = ((nig*2+ks)*32 + lane)*4 + slot, slots = {bh0, bh1, bl0, bl1}
// region count = 2 * ceil(K/16) per weight
#define OFF_WIA 0         // 18 regions
#define OFF_WIB 73728     // 20
#define OFF_WH  155648    // 3 * 32
#define OFF_WLR 548864    // 96
#define OFF_WO  942080    // 32
#define FMT_TOTAL 1073152
__device__ float g_fmt[FMT_TOTAL];

static inline int cdiv(int a, int b) { return (a + b - 1) / b; }

// ================= helpers =================
__device__ __forceinline__ uint32_t smem_u32(const void* p) {
    uint32_t a;
    asm("{ .reg .u64 t; cvta.to.shared.u64 t, %1; cvt.u32.u64 %0, t; }" : "=r"(a) : "l"(p));
    return a;
}
__device__ __forceinline__ void split_tf32(float x, uint32_t& hi, uint32_t& lo) {
    uint32_t h;
    asm("cvt.rna.tf32.f32 %0, %1;" : "=r"(h) : "f"(x));
    float hf = __uint_as_float(h);
    float r = x - hf;
    uint32_t l;
    asm("cvt.rna.tf32.f32 %0, %1;" : "=r"(l) : "f"(r));
    hi = h; lo = l;
}
__device__ __forceinline__ void mma_tf32(float* c, const uint32_t* a, const uint32_t* b) {
    asm volatile(
        "mma.sync.aligned.m16n8k8.row.col.f32.tf32.tf32.f32 "
        "{%0,%1,%2,%3}, {%4,%5,%6,%7}, {%8,%9}, {%0,%1,%2,%3};\n"
        : "+f"(c[0]), "+f"(c[1]), "+f"(c[2]), "+f"(c[3])
        : "r"(a[0]), "r"(a[1]), "r"(a[2]), "r"(a[3]), "r"(b[0]), "r"(b[1]));
}
__device__ __forceinline__ void cp16(uint32_t dst, const void* src) {
    asm volatile("cp.async.cg.shared.global [%0], [%1], 16;" :: "r"(dst), "l"(src));
}

// ================= weight prep: split + fragment layout =================
// W is [K][256] row-major. region rb = ny*KB + kb; 128 threads, 32 elems each.
__global__ __launch_bounds__(128)
void prep_weight(const float* __restrict__ W, int K, int KB, long dstoff)
{
    const int rb = blockIdx.x;
    const int ny = rb / KB, kb = rb % KB;
    const int t = threadIdx.x;
    float* dst = g_fmt + dstoff + (long)rb * 4096;
#pragma unroll
    for (int i = 0; i < 32; i++) {
        int idx = i * 128 + t;
        int slot = idx & 3;
        int lane = (idx >> 2) & 31;
        int ks   = (idx >> 7) & 1;
        int nig  = idx >> 8;
        int nloc = nig * 8 + (lane >> 2);
        int kloc = ks * 8 + (slot & 1) * 4 + (lane & 3);
        int kg = kb * 16 + kloc;
        int ng = ny * 128 + nloc;
        float v = (kg < K) ? W[(long)kg * 256 + ng] : 0.f;
        uint32_t hi, lo;
        split_tf32(v, hi, lo);
        dst[idx] = __uint_as_float((slot >> 1) ? lo : hi);
    }
}

// ================= mma.sync tf32 3-split GEMM =================
// C[M,256] = op(A)[M,K] @ B[K,256]; CTA: 128 rows x 128 cols (grid.y = n-half)
// 256 threads = 8 warps (2 m x 4 n), warp tile 64x32, double-buffered k16 blocks.
// A pre-split into hi/lo smem planes at staging (no cvt in compute loop).
// MODE 0: plain A scalar loads (ragged K), relu
// MODE 1: A = ma[b2a[r]] - mbprev[b2revb[r]] (K=256), relu(addp + C)
// MODE 2: A from 3 sources (K=768), plain store
// MODE 3: plain A (K=256), relu(C + bias)
template<int MODE>
__global__ __launch_bounds__(256)
void gemm_mma(const float* __restrict__ Ap, const float* __restrict__ A2,
              const float* __restrict__ A3,
              const int* __restrict__ gi1, const int* __restrict__ gi2,
              const float* __restrict__ fmt,
              float* __restrict__ Cp, const float* __restrict__ addp,
              const float* __restrict__ biasp, int M, int K, int KB)
{
    // A fragments: plane 0 = hi [0..2047], plane 1 = lo [2048..4095]
    __shared__ float  As[2][4096];
    __shared__ float4 Bs[2][1024];   // B fragments: (nig*2+ks)*32+lane -> {bh0,bh1,bl0,bl1}

    const int tid = threadIdx.x;
    const int lane = tid & 31;
    const int wid = tid >> 5;
    const int wm = wid & 1;
    const int wn = wid >> 1;
    const int m0 = blockIdx.x * 128;
    const int n0 = blockIdx.y * 128;

    // staging identity: thread stages row srow, k-half skh (8 k each)
    const int srow = tid >> 1;
    const int skh = tid & 1;
    const int gm_s = min(m0 + srow, M - 1);
    int ia = 0, ir = 0;
    if (MODE == 1) { ia = gi1[gm_s]; ir = gi2[gm_s]; }

    // precomputed STS float-indices for the 8 staged elements
    int sts_idx[8];
    {
        int mig = srow >> 4;
#pragma unroll
        for (int j = 0; j < 8; j++) {
            int lt = ((srow & 7) << 2) | (j & 3);
            int slot = (((j >> 2) & 1) << 1) | ((srow >> 3) & 1);
            sts_idx[j] = ((mig * 2 + skh) * 32 + lt) * 4 + slot;
        }
    }

    float acc[4][4][4];
#pragma unroll
    for (int mi = 0; mi < 4; mi++)
#pragma unroll
        for (int ni = 0; ni < 4; ni++)
#pragma unroll
            for (int q = 0; q < 4; q++) acc[mi][ni][q] = 0.f;

    float areg[8];

    auto loadA = [&](int kb) {
        const int kbase = kb * 16 + skh * 8;
        if (MODE == 0) {
            const float* row = Ap + (long)gm_s * K + kbase;
#pragma unroll
            for (int j = 0; j < 8; j++) areg[j] = (kbase + j < K) ? row[j] : 0.f;
        } else if (MODE == 1) {
            const float* ra = Ap + ((long)ia << 8) + kbase;
            const float* rr = A2 + ((long)ir << 8) + kbase;
            float4 x0 = *(const float4*)ra, x1 = *(const float4*)(ra + 4);
            float4 y0 = *(const float4*)rr, y1 = *(const float4*)(rr + 4);
            areg[0] = x0.x - y0.x; areg[1] = x0.y - y0.y; areg[2] = x0.z - y0.z; areg[3] = x0.w - y0.w;
            areg[4] = x1.x - y1.x; areg[5] = x1.y - y1.y; areg[6] = x1.z - y1.z; areg[7] = x1.w - y1.w;
        } else if (MODE == 2) {
            int which = kb >> 4;
            const float* src = (which == 0) ? Ap : (which == 1) ? A2 : A3;
            const float* ra = src + ((long)gm_s << 8) + (kb & 15) * 16 + skh * 8;
            float4 x0 = *(const float4*)ra, x1 = *(const float4*)(ra + 4);
            areg[0] = x0.x; areg[1] = x0.y; areg[2] = x0.z; areg[3] = x0.w;
            areg[4] = x1.x; areg[5] = x1.y; areg[6] = x1.z; areg[7] = x1.w;
        } else {
            const float* ra = Ap + ((long)gm_s << 8) + kbase;
            float4 x0 = *(const float4*)ra, x1 = *(const float4*)(ra + 4);
            areg[0] = x0.x; areg[1] = x0.y; areg[2] = x0.z; areg[3] = x0.w;
            areg[4] = x1.x; areg[5] = x1.y; areg[6] = x1.z; areg[7] = x1.w;
        }
    };

    auto issueB = [&](int kb, int buf) {
        const float4* src = (const float4*)fmt + (long)(blockIdx.y * KB + kb) * 1024;
        uint32_t dst = smem_u32(&Bs[buf][0]);
#pragma unroll
        for (int i = 0; i < 4; i++) {
            int idx = i * 256 + tid;
            cp16(dst + idx * 16, src + idx);
        }
        asm volatile("cp.async.commit_group;" ::: "memory");
    };

    auto storeA = [&](int buf) {
#pragma unroll
        for (int j = 0; j < 8; j++) {
            uint32_t hi, lo;
            split_tf32(areg[j], hi, lo);
            As[buf][sts_idx[j]]        = __uint_as_float(hi);
            As[buf][2048 + sts_idx[j]] = __uint_as_float(lo);
        }
    };

    auto compute = [&](int buf) {
        const float* ah_s = As[buf];
        const float* al_s = As[buf] + 2048;
        const float4* b_s = Bs[buf];
#pragma unroll
        for (int ks = 0; ks < 2; ks++) {
            uint32_t bh[4][2], bl[4][2];
#pragma unroll
            for (int ni = 0; ni < 4; ni++) {
                int nig = wn * 4 + ni;
                float4 f = b_s[(nig * 2 + ks) * 32 + lane];
                bh[ni][0] = __float_as_uint(f.x); bh[ni][1] = __float_as_uint(f.y);
                bl[ni][0] = __float_as_uint(f.z); bl[ni][1] = __float_as_uint(f.w);
            }
#pragma unroll
            for (int mi = 0; mi < 4; mi++) {
                int mig = wm * 4 + mi;
                int fidx = ((mig * 2 + ks) * 32 + lane) * 4;
                float4 rh = *(const float4*)(ah_s + fidx);
                float4 rl = *(const float4*)(al_s + fidx);
                uint32_t ah[4], al[4];
                ah[0] = __float_as_uint(rh.x); ah[1] = __float_as_uint(rh.y);
                ah[2] = __float_as_uint(rh.z); ah[3] = __float_as_uint(rh.w);
                al[0] = __float_as_uint(rl.x); al[1] = __float_as_uint(rl.y);
                al[2] = __float_as_uint(rl.z); al[3] = __float_as_uint(rl.w);
#pragma unroll
                for (int ni = 0; ni < 4; ni++) {
                    mma_tf32(acc[mi][ni], ah, bh[ni]);
                    mma_tf32(acc[mi][ni], ah, bl[ni]);
                    mma_tf32(acc[mi][ni], al, bh[ni]);
                }
            }
        }
    };

    // prologue
    loadA(0);
    issueB(0, 0);
    storeA(0);
    asm volatile("cp.async.wait_group 0;" ::: "memory");
    __syncthreads();

    for (int kb = 0; kb < KB; kb++) {
        const int buf = kb & 1;
        const bool more = (kb + 1 < KB);
        if (more) { loadA(kb + 1); issueB(kb + 1, buf ^ 1); }
        compute(buf);
        if (more) {
            storeA(buf ^ 1);
            asm volatile("cp.async.wait_group 0;" ::: "memory");
        }
        __syncthreads();
    }

    // epilogue
#pragma unroll
    for (int mi = 0; mi < 4; mi++) {
        int r0 = m0 + wm * 64 + mi * 16 + (lane >> 2);
#pragma unroll
        for (int ni = 0; ni < 4; ni++) {
            int c = n0 + wn * 32 + ni * 8 + (lane & 3) * 2;
#pragma unroll
            for (int half = 0; half < 2; half++) {
                int r = r0 + half * 8;
                if (r >= M) continue;
                float x = acc[mi][ni][half * 2 + 0];
                float y = acc[mi][ni][half * 2 + 1];
                long o = (long)r * 256 + c;
                if (MODE == 1) {
                    float2 t = *(const float2*)(addp + o);
                    x += t.x; y += t.y;
                }
                if (MODE == 3) {
                    float2 t = *(const float2*)(biasp + c);
                    x += t.x; y += t.y;
                }
                if (MODE != 2) { x = fmaxf(x, 0.f); y = fmaxf(y, 0.f); }
                *(float2*)(Cp + o) = make_float2(x, y);
            }
        }
    }
}

// ---------------- sum*max neighbor aggregation ----------------
template<bool ADD>
__global__ __launch_bounds__(256)
void sum_max_kernel(const float* __restrict__ mb, const int* __restrict__ a2b,
                    const float* __restrict__ addsrc, float* __restrict__ outp)
{
    int a = blockIdx.x * 4 + (threadIdx.x >> 6);
    if (a >= A_N) return;
    int h = (threadIdx.x & 63) << 2;
    const int* ab = a2b + (long)a * NBN;
    float4 s = make_float4(0.f, 0.f, 0.f, 0.f);
    float4 mx = make_float4(-1e30f, -1e30f, -1e30f, -1e30f);
#pragma unroll
    for (int j = 0; j < NBN; j++) {
        float4 v = *(const float4*)(mb + (long)ab[j] * H + h);
        s.x += v.x; s.y += v.y; s.z += v.z; s.w += v.w;
        mx.x = fmaxf(mx.x, v.x); mx.y = fmaxf(mx.y, v.y);
        mx.z = fmaxf(mx.z, v.z); mx.w = fmaxf(mx.w, v.w);
    }
    long o = (long)a * H + h;
    float4 r = make_float4(s.x * mx.x, s.y * mx.y, s.z * mx.z, s.w * mx.w);
    if (ADD) {
        float4 c = *(const float4*)(addsrc + o);
        r.x += c.x; r.y += c.y; r.z += c.z; r.w += c.w;
    }
    *(float4*)(outp + o) = r;
}

// ---------------- exclusive scan of molecule sizes ----------------
__global__ void scan_kernel(const int* __restrict__ sizes)
{
    __shared__ int part[1024];
    int t = threadIdx.x;
    const int CH = (M_N + 1023) / 1024;
    int base = t * CH;
    int s = 0;
    for (int i = 0; i < CH; i++) {
        int idx = base + i;
        if (idx < M_N) s += sizes[idx];
    }
    part[t] = s;
    __syncthreads();
    for (int off = 1; off < 1024; off <<= 1) {
        int v = (t >= off) ? part[t - off] : 0;
        __syncthreads();
        part[t] += v;
        __syncthreads();
    }
    int run = (t == 0) ? 0 : part[t - 1];
    for (int i = 0; i < CH; i++) {
        int idx = base + i;
        if (idx < M_N) { g_offsets[idx] = run; run += sizes[idx]; }
    }
}

// ---------------- per-molecule mean pooling ----------------
__global__ __launch_bounds__(64)
void pool_kernel(const float* __restrict__ ah, const int* __restrict__ sizes,
                 float* __restrict__ out)
{
    int m = blockIdx.x;
    int h = threadIdx.x << 2;
    int start = g_offsets[m];
    int n = sizes[m];
    float4 s = make_float4(0.f, 0.f, 0.f, 0.f);
    for (int i = 0; i < n; i++) {
        float4 v = *(const float4*)(ah + (long)(start + i) * H + h);
        s.x += v.x; s.y += v.y; s.z += v.z; s.w += v.w;
    }
    float inv = 1.0f / (float)n;
    *(float4*)(out + (long)m * H + h) = make_float4(s.x * inv, s.y * inv, s.z * inv, s.w * inv);
}

// ---------------- launch ----------------
extern "C" void kernel_launch(void* const* d_in, const int* in_sizes, int n_in,
                              void* d_out, int out_size)
{
    const float* f_atoms = (const float*)d_in[0];
    const float* f_bonds = (const float*)d_in[1];
    const float* W_ia    = (const float*)d_in[2];
    const float* W_ib    = (const float*)d_in[3];
    const float* W_h     = (const float*)d_in[4];
    const float* W_o     = (const float*)d_in[5];
    const float* b_o     = (const float*)d_in[6];
    const float* W_lr    = (const float*)d_in[7];
    const int*   a2b     = (const int*)d_in[8];
    const int*   b2a     = (const int*)d_in[9];
    const int*   b2revb  = (const int*)d_in[10];
    const int*   sizes   = (const int*)d_in[11];
    float* out = (float*)d_out;

    float *input_atom, *input_bond, *ma, *mb0, *mb1, *agg, *h1, *ah, *fmt;
    cudaGetSymbolAddress((void**)&input_atom, g_input_atom);
    cudaGetSymbolAddress((void**)&input_bond, g_input_bond);
    cudaGetSymbolAddress((void**)&ma, g_message_atom);
    cudaGetSymbolAddress((void**)&mb0, g_mb0);
    cudaGetSymbolAddress((void**)&mb1, g_mb1);
    cudaGetSymbolAddress((void**)&agg, g_agg);
    cudaGetSymbolAddress((void**)&h1, g_h1);
    cudaGetSymbolAddress((void**)&ah, g_ah);
    cudaGetSymbolAddress((void**)&fmt, g_fmt);

    // weight prep (tf32 split + fragment layout), KB = ceil(K/16)
    prep_weight<<<2 * 9, 128>>>(W_ia, FA, 9, OFF_WIA);
    prep_weight<<<2 * 10, 128>>>(W_ib, FB, 10, OFF_WIB);
    for (int d = 0; d < DEPTH - 1; d++)
        prep_weight<<<2 * 16, 128>>>(W_h + (long)d * H * H, H, 16, OFF_WH + (long)d * 131072);
    prep_weight<<<2 * 48, 128>>>(W_lr, 3 * H, 48, OFF_WLR);
    prep_weight<<<2 * 16, 128>>>(W_o, H, 16, OFF_WO);

    dim3 gA(cdiv(A_N, 128), 2), gB(cdiv(B_N, 128), 2);

    // input projections (relu)
    gemm_mma<0><<<gA, 256>>>(f_atoms, nullptr, nullptr, nullptr, nullptr,
                             fmt + OFF_WIA, input_atom, nullptr, nullptr, A_N, FA, 9);
    gemm_mma<0><<<gB, 256>>>(f_bonds, nullptr, nullptr, nullptr, nullptr,
                             fmt + OFF_WIB, input_bond, nullptr, nullptr, B_N, FB, 10);

    // message passing (ping-pong bond buffers)
    const float* mbcur = input_bond;
    for (int d = 0; d < DEPTH - 1; d++) {
        sum_max_kernel<true><<<cdiv(A_N, 4), 256>>>(mbcur, a2b,
                                                    (d == 0) ? input_atom : ma, ma);
        float* mbout = (d % 2 == 0) ? mb0 : mb1;
        gemm_mma<1><<<gB, 256>>>(ma, mbcur, nullptr, b2a, b2revb,
                                 fmt + OFF_WH + (long)d * 131072,
                                 mbout, input_bond, nullptr, B_N, H, 16);
        mbcur = mbout;
    }

    // final aggregation + readout
    sum_max_kernel<false><<<cdiv(A_N, 4), 256>>>(mbcur, a2b, nullptr, agg);

    gemm_mma<2><<<gA, 256>>>(agg, ma, input_atom, nullptr, nullptr,
                             fmt + OFF_WLR, h1, nullptr, nullptr, A_N, 3 * H, 48);

    gemm_mma<3><<<gA, 256>>>(h1, nullptr, nullptr, nullptr, nullptr,
                             fmt + OFF_WO, ah, nullptr, b_o, A_N, H, 16);

    scan_kernel<<<1, 1024>>>(sizes);
    pool_kernel<<<M_N, 64>>>(ah, sizes, out);
}

// round 8
// speedup vs baseline: 1.3758x; 1.3758x over previous
#include <cuda_runtime.h>
#include <cstdint>

#define A_N 100000
#define B_N 200000
#define NBN 6
#define FA 133
#define FB 147
#define H 256
#define M_N 5000
#define DEPTH 4

// ---------------- device scratch (no allocations allowed) ----------------
__device__ float g_input_atom[(size_t)A_N * H];
__device__ float g_input_bond[(size_t)B_N * H];
__device__ float g_message_atom[(size_t)A_N * H];
__device__ float g_mb0[(size_t)B_N * H];
__device__ float g_mb1[(size_t)B_N * H];
__device__ float g_agg[(size_t)A_N * H];
__device__ float g_h1[(size_t)A_N * H];
__device__ float g_ah[(size_t)A_N * H];
__device__ int   g_offsets[M_N];

// pre-formatted B weights: per region (ny, kb16) 4096 floats, fragment layout,
// element idx = ((nig*2+ks)*32 + lane)*4 + slot, slots = {bh0, bh1, bl0, bl1}
// region count = 2 * ceil(K/16) per weight
#define OFF_WIA 0         // 18 regions
#define OFF_WIB 73728     // 20
#define OFF_WH  155648    // 3 * 32
#define OFF_WLR 548864    // 96
#define OFF_WO  942080    // 32
#define FMT_TOTAL 1073152
__device__ float g_fmt[FMT_TOTAL];

static inline int cdiv(int a, int b) { return (a + b - 1) / b; }

// ================= helpers =================
__device__ __forceinline__ uint32_t smem_u32(const void* p) {
    uint32_t a;
    asm("{ .reg .u64 t; cvta.to.shared.u64 t, %1; cvt.u32.u64 %0, t; }" : "=r"(a) : "l"(p));
    return a;
}
__device__ __forceinline__ void split_tf32(float x, uint32_t& hi, uint32_t& lo) {
    uint32_t h;
    asm("cvt.rna.tf32.f32 %0, %1;" : "=r"(h) : "f"(x));
    float hf = __uint_as_float(h);
    float r = x - hf;
    uint32_t l;
    asm("cvt.rna.tf32.f32 %0, %1;" : "=r"(l) : "f"(r));
    hi = h; lo = l;
}
__device__ __forceinline__ uint32_t cvt_tf32(float x) {
    uint32_t h;
    asm("cvt.rna.tf32.f32 %0, %1;" : "=r"(h) : "f"(x));
    return h;
}
__device__ __forceinline__ void mma_tf32(float* c, const uint32_t* a, const uint32_t* b) {
    asm volatile(
        "mma.sync.aligned.m16n8k8.row.col.f32.tf32.tf32.f32 "
        "{%0,%1,%2,%3}, {%4,%5,%6,%7}, {%8,%9}, {%0,%1,%2,%3};\n"
        : "+f"(c[0]), "+f"(c[1]), "+f"(c[2]), "+f"(c[3])
        : "r"(a[0]), "r"(a[1]), "r"(a[2]), "r"(a[3]), "r"(b[0]), "r"(b[1]));
}
__device__ __forceinline__ void cp16(uint32_t dst, const void* src) {
    asm volatile("cp.async.cg.shared.global [%0], [%1], 16;" :: "r"(dst), "l"(src));
}

// ================= weight prep: split + fragment layout, region-dispatched ====
// region rb (within a weight) = ny*KB + kb; global region id selects the weight.
// WIA [0,18), WIB [18,38), WH [38,134) (3x32), WLR [134,230), WO [230,262)
__global__ __launch_bounds__(128)
void prep_all(const float* __restrict__ W_ia, const float* __restrict__ W_ib,
              const float* __restrict__ W_h,  const float* __restrict__ W_lr,
              const float* __restrict__ W_o,  int rb_base)
{
    const int rb_g = rb_base + blockIdx.x;
    const float* W; int K, KB; long dstoff; int rb;
    if (rb_g < 18)       { W = W_ia; K = FA;    KB = 9;  dstoff = OFF_WIA; rb = rb_g; }
    else if (rb_g < 38)  { W = W_ib; K = FB;    KB = 10; dstoff = OFF_WIB; rb = rb_g - 18; }
    else if (rb_g < 134) { int d = (rb_g - 38) >> 5;
                           W = W_h + (long)d * H * H; K = H; KB = 16;
                           dstoff = OFF_WH + (long)d * 131072; rb = (rb_g - 38) & 31; }
    else if (rb_g < 230) { W = W_lr; K = 3 * H; KB = 48; dstoff = OFF_WLR; rb = rb_g - 134; }
    else                 { W = W_o;  K = H;     KB = 16; dstoff = OFF_WO;  rb = rb_g - 230; }

    const int ny = rb / KB, kb = rb % KB;
    const int t = threadIdx.x;
    float* dst = g_fmt + dstoff + (long)rb * 4096;
#pragma unroll
    for (int i = 0; i < 32; i++) {
        int idx = i * 128 + t;
        int slot = idx & 3;
        int lane = (idx >> 2) & 31;
        int ks   = (idx >> 7) & 1;
        int nig  = idx >> 8;
        int nloc = nig * 8 + (lane >> 2);
        int kloc = ks * 8 + (slot & 1) * 4 + (lane & 3);
        int kg = kb * 16 + kloc;
        int ng = ny * 128 + nloc;
        float v = (kg < K) ? W[(long)kg * 256 + ng] : 0.f;
        uint32_t hi, lo;
        split_tf32(v, hi, lo);
        dst[idx] = __uint_as_float((slot >> 1) ? lo : hi);
    }
}

// ================= mma.sync tf32 3-split GEMM =================
// C[M,256] = op(A)[M,K] @ B[K,256]; CTA: 128 rows x 128 cols (grid.y = n-half)
// 256 threads = 8 warps (2 m x 4 n), warp tile 64x32, double-buffered k16 blocks.
// kb3 = number of leading k-blocks computed with the full 3-term split;
// blocks kb >= kb3 use single-pass tf32 (hi only) — used for magnitude-dominated
// K slices in the readout GEMM.
// MODE 0: plain A scalar loads (ragged K), relu
// MODE 1: A = ma[b2a[r]] - mbprev[b2revb[r]] (K=256), relu(addp + C)
// MODE 2: A from 3 sources (K=768), plain store
// MODE 3: plain A (K=256), relu(C + bias)
template<int MODE>
__global__ __launch_bounds__(256)
void gemm_mma(const float* __restrict__ Ap, const float* __restrict__ A2,
              const float* __restrict__ A3,
              const int* __restrict__ gi1, const int* __restrict__ gi2,
              const float* __restrict__ fmt,
              float* __restrict__ Cp, const float* __restrict__ addp,
              const float* __restrict__ biasp, int M, int K, int KB, int kb3)
{
    __shared__ float  As[2][2048];   // A fragment layout: ((mig*2+ks)*32+lane)*4+slot
    __shared__ float4 Bs[2][1024];   // B fragment layout: (nig*2+ks)*32+lane -> {bh0,bh1,bl0,bl1}

    const int tid = threadIdx.x;
    const int lane = tid & 31;
    const int wid = tid >> 5;
    const int wm = wid & 1;
    const int wn = wid >> 1;
    const int m0 = blockIdx.x * 128;
    const int n0 = blockIdx.y * 128;

    // staging identity: thread stages row srow, k-half skh (8 k each)
    const int srow = tid >> 1;
    const int skh = tid & 1;
    const int gm_s = min(m0 + srow, M - 1);
    int ia = 0, ir = 0;
    if (MODE == 1) { ia = gi1[gm_s]; ir = gi2[gm_s]; }

    // precomputed STS float-indices for the 8 staged elements
    int sts_idx[8];
    {
        int mig = srow >> 4;
#pragma unroll
        for (int j = 0; j < 8; j++) {
            int lt = ((srow & 7) << 2) | (j & 3);
            int slot = (((j >> 2) & 1) << 1) | ((srow >> 3) & 1);
            sts_idx[j] = ((mig * 2 + skh) * 32 + lt) * 4 + slot;
        }
    }

    float acc[4][4][4];
#pragma unroll
    for (int mi = 0; mi < 4; mi++)
#pragma unroll
        for (int ni = 0; ni < 4; ni++)
#pragma unroll
            for (int q = 0; q < 4; q++) acc[mi][ni][q] = 0.f;

    float areg[8];

    auto loadA = [&](int kb) {
        const int kbase = kb * 16 + skh * 8;
        if (MODE == 0) {
            const float* row = Ap + (long)gm_s * K + kbase;
#pragma unroll
            for (int j = 0; j < 8; j++) areg[j] = (kbase + j < K) ? row[j] : 0.f;
        } else if (MODE == 1) {
            const float* ra = Ap + ((long)ia << 8) + kbase;
            const float* rr = A2 + ((long)ir << 8) + kbase;
            float4 x0 = *(const float4*)ra, x1 = *(const float4*)(ra + 4);
            float4 y0 = *(const float4*)rr, y1 = *(const float4*)(rr + 4);
            areg[0] = x0.x - y0.x; areg[1] = x0.y - y0.y; areg[2] = x0.z - y0.z; areg[3] = x0.w - y0.w;
            areg[4] = x1.x - y1.x; areg[5] = x1.y - y1.y; areg[6] = x1.z - y1.z; areg[7] = x1.w - y1.w;
        } else if (MODE == 2) {
            int which = kb >> 4;
            const float* src = (which == 0) ? Ap : (which == 1) ? A2 : A3;
            const float* ra = src + ((long)gm_s << 8) + (kb & 15) * 16 + skh * 8;
            float4 x0 = *(const float4*)ra, x1 = *(const float4*)(ra + 4);
            areg[0] = x0.x; areg[1] = x0.y; areg[2] = x0.z; areg[3] = x0.w;
            areg[4] = x1.x; areg[5] = x1.y; areg[6] = x1.z; areg[7] = x1.w;
        } else {
            const float* ra = Ap + ((long)gm_s << 8) + kbase;
            float4 x0 = *(const float4*)ra, x1 = *(const float4*)(ra + 4);
            areg[0] = x0.x; areg[1] = x0.y; areg[2] = x0.z; areg[3] = x0.w;
            areg[4] = x1.x; areg[5] = x1.y; areg[6] = x1.z; areg[7] = x1.w;
        }
    };

    auto issueB = [&](int kb, int buf) {
        const float4* src = (const float4*)fmt + (long)(blockIdx.y * KB + kb) * 1024;
        uint32_t dst = smem_u32(&Bs[buf][0]);
#pragma unroll
        for (int i = 0; i < 4; i++) {
            int idx = i * 256 + tid;
            cp16(dst + idx * 16, src + idx);
        }
        asm volatile("cp.async.commit_group;" ::: "memory");
    };

    auto storeA = [&](int buf) {
#pragma unroll
        for (int j = 0; j < 8; j++) As[buf][sts_idx[j]] = areg[j];
    };

    auto compute = [&](int buf, bool full3) {
        const float* a_s = As[buf];
        const float4* b_s = Bs[buf];
#pragma unroll
        for (int ks = 0; ks < 2; ks++) {
            uint32_t bh[4][2], bl[4][2];
#pragma unroll
            for (int ni = 0; ni < 4; ni++) {
                int nig = wn * 4 + ni;
                float4 f = b_s[(nig * 2 + ks) * 32 + lane];
                bh[ni][0] = __float_as_uint(f.x); bh[ni][1] = __float_as_uint(f.y);
                bl[ni][0] = __float_as_uint(f.z); bl[ni][1] = __float_as_uint(f.w);
            }
#pragma unroll
            for (int mi = 0; mi < 4; mi++) {
                int mig = wm * 4 + mi;
                float4 ra = *(const float4*)(a_s + ((mig * 2 + ks) * 32 + lane) * 4);
                if (full3) {
                    uint32_t ah[4], al[4];
                    split_tf32(ra.x, ah[0], al[0]);
                    split_tf32(ra.y, ah[1], al[1]);
                    split_tf32(ra.z, ah[2], al[2]);
                    split_tf32(ra.w, ah[3], al[3]);
#pragma unroll
                    for (int ni = 0; ni < 4; ni++) {
                        mma_tf32(acc[mi][ni], ah, bh[ni]);
                        mma_tf32(acc[mi][ni], ah, bl[ni]);
                        mma_tf32(acc[mi][ni], al, bh[ni]);
                    }
                } else {
                    uint32_t ah[4];
                    ah[0] = cvt_tf32(ra.x); ah[1] = cvt_tf32(ra.y);
                    ah[2] = cvt_tf32(ra.z); ah[3] = cvt_tf32(ra.w);
#pragma unroll
                    for (int ni = 0; ni < 4; ni++)
                        mma_tf32(acc[mi][ni], ah, bh[ni]);
                }
            }
        }
    };

    // prologue
    loadA(0);
    issueB(0, 0);
    storeA(0);
    asm volatile("cp.async.wait_group 0;" ::: "memory");
    __syncthreads();

    for (int kb = 0; kb < KB; kb++) {
        const int buf = kb & 1;
        const bool more = (kb + 1 < KB);
        if (more) { loadA(kb + 1); issueB(kb + 1, buf ^ 1); }
        compute(buf, kb < kb3);
        if (more) {
            storeA(buf ^ 1);
            asm volatile("cp.async.wait_group 0;" ::: "memory");
        }
        __syncthreads();
    }

    // epilogue
#pragma unroll
    for (int mi = 0; mi < 4; mi++) {
        int r0 = m0 + wm * 64 + mi * 16 + (lane >> 2);
#pragma unroll
        for (int ni = 0; ni < 4; ni++) {
            int c = n0 + wn * 32 + ni * 8 + (lane & 3) * 2;
#pragma unroll
            for (int half = 0; half < 2; half++) {
                int r = r0 + half * 8;
                if (r >= M) continue;
                float x = acc[mi][ni][half * 2 + 0];
                float y = acc[mi][ni][half * 2 + 1];
                long o = (long)r * 256 + c;
                if (MODE == 1) {
                    float2 t = *(const float2*)(addp + o);
                    x += t.x; y += t.y;
                }
                if (MODE == 3) {
                    float2 t = *(const float2*)(biasp + c);
                    x += t.x; y += t.y;
                }
                if (MODE != 2) { x = fmaxf(x, 0.f); y = fmaxf(y, 0.f); }
                *(float2*)(Cp + o) = make_float2(x, y);
            }
        }
    }
}

// ---------------- sum*max neighbor aggregation ----------------
template<bool ADD>
__global__ __launch_bounds__(256)
void sum_max_kernel(const float* __restrict__ mb, const int* __restrict__ a2b,
                    const float* __restrict__ addsrc, float* __restrict__ outp)
{
    int a = blockIdx.x * 4 + (threadIdx.x >> 6);
    if (a >= A_N) return;
    int h = (threadIdx.x & 63) << 2;
    const int* ab = a2b + (long)a * NBN;
    float4 s = make_float4(0.f, 0.f, 0.f, 0.f);
    float4 mx = make_float4(-1e30f, -1e30f, -1e30f, -1e30f);
#pragma unroll
    for (int j = 0; j < NBN; j++) {
        float4 v = *(const float4*)(mb + (long)ab[j] * H + h);
        s.x += v.x; s.y += v.y; s.z += v.z; s.w += v.w;
        mx.x = fmaxf(mx.x, v.x); mx.y = fmaxf(mx.y, v.y);
        mx.z = fmaxf(mx.z, v.z); mx.w = fmaxf(mx.w, v.w);
    }
    long o = (long)a * H + h;
    float4 r = make_float4(s.x * mx.x, s.y * mx.y, s.z * mx.z, s.w * mx.w);
    if (ADD) {
        float4 c = *(const float4*)(addsrc + o);
        r.x += c.x; r.y += c.y; r.z += c.z; r.w += c.w;
    }
    *(float4*)(outp + o) = r;
}

// ---------------- exclusive scan of molecule sizes ----------------
__global__ void scan_kernel(const int* __restrict__ sizes)
{
    __shared__ int part[1024];
    int t = threadIdx.x;
    const int CH = (M_N + 1023) / 1024;
    int base = t * CH;
    int s = 0;
    for (int i = 0; i < CH; i++) {
        int idx = base + i;
        if (idx < M_N) s += sizes[idx];
    }
    part[t] = s;
    __syncthreads();
    for (int off = 1; off < 1024; off <<= 1) {
        int v = (t >= off) ? part[t - off] : 0;
        __syncthreads();
        part[t] += v;
        __syncthreads();
    }
    int run = (t == 0) ? 0 : part[t - 1];
    for (int i = 0; i < CH; i++) {
        int idx = base + i;
        if (idx < M_N) { g_offsets[idx] = run; run += sizes[idx]; }
    }
}

// ---------------- per-molecule mean pooling ----------------
__global__ __launch_bounds__(64)
void pool_kernel(const float* __restrict__ ah, const int* __restrict__ sizes,
                 float* __restrict__ out)
{
    int m = blockIdx.x;
    int h = threadIdx.x << 2;
    int start = g_offsets[m];
    int n = sizes[m];
    float4 s = make_float4(0.f, 0.f, 0.f, 0.f);
    for (int i = 0; i < n; i++) {
        float4 v = *(const float4*)(ah + (long)(start + i) * H + h);
        s.x += v.x; s.y += v.y; s.z += v.z; s.w += v.w;
    }
    float inv = 1.0f / (float)n;
    *(float4*)(out + (long)m * H + h) = make_float4(s.x * inv, s.y * inv, s.z * inv, s.w * inv);
}

// ---------------- launch ----------------
extern "C" void kernel_launch(void* const* d_in, const int* in_sizes, int n_in,
                              void* d_out, int out_size)
{
    const float* f_atoms = (const float*)d_in[0];
    const float* f_bonds = (const float*)d_in[1];
    const float* W_ia    = (const float*)d_in[2];
    const float* W_ib    = (const float*)d_in[3];
    const float* W_h     = (const float*)d_in[4];
    const float* W_o     = (const float*)d_in[5];
    const float* b_o     = (const float*)d_in[6];
    const float* W_lr    = (const float*)d_in[7];
    const int*   a2b     = (const int*)d_in[8];
    const int*   b2a     = (const int*)d_in[9];
    const int*   b2revb  = (const int*)d_in[10];
    const int*   sizes   = (const int*)d_in[11];
    float* out = (float*)d_out;

    float *input_atom, *input_bond, *ma, *mb0, *mb1, *agg, *h1, *ah, *fmt;
    cudaGetSymbolAddress((void**)&input_atom, g_input_atom);
    cudaGetSymbolAddress((void**)&input_bond, g_input_bond);
    cudaGetSymbolAddress((void**)&ma, g_message_atom);
    cudaGetSymbolAddress((void**)&mb0, g_mb0);
    cudaGetSymbolAddress((void**)&mb1, g_mb1);
    cudaGetSymbolAddress((void**)&agg, g_agg);
    cudaGetSymbolAddress((void**)&h1, g_h1);
    cudaGetSymbolAddress((void**)&ah, g_ah);
    cudaGetSymbolAddress((void**)&fmt, g_fmt);

    // weight prep: 262 regions total, split into exactly 2 launches
    prep_all<<<131, 128>>>(W_ia, W_ib, W_h, W_lr, W_o, 0);
    prep_all<<<131, 128>>>(W_ia, W_ib, W_h, W_lr, W_o, 131);

    dim3 gA(cdiv(A_N, 128), 2), gB(cdiv(B_N, 128), 2);

    // input projections (relu)
    gemm_mma<0><<<gA, 256>>>(f_atoms, nullptr, nullptr, nullptr, nullptr,
                             fmt + OFF_WIA, input_atom, nullptr, nullptr, A_N, FA, 9, 9);
    gemm_mma<0><<<gB, 256>>>(f_bonds, nullptr, nullptr, nullptr, nullptr,
                             fmt + OFF_WIB, input_bond, nullptr, nullptr, B_N, FB, 10, 10);

    // message passing (ping-pong bond buffers)
    const float* mbcur = input_bond;
    for (int d = 0; d < DEPTH - 1; d++) {
        sum_max_kernel<true><<<cdiv(A_N, 4), 256>>>(mbcur, a2b,
                                                    (d == 0) ? input_atom : ma, ma);
        float* mbout = (d % 2 == 0) ? mb0 : mb1;
        gemm_mma<1><<<gB, 256>>>(ma, mbcur, nullptr, b2a, b2revb,
                                 fmt + OFF_WH + (long)d * 131072,
                                 mbout, input_bond, nullptr, B_N, H, 16, 16);
        mbcur = mbout;
    }

    // final aggregation + readout
    sum_max_kernel<false><<<cdiv(A_N, 4), 256>>>(mbcur, a2b, nullptr, agg);

    // W_lr GEMM: 3-term tf32 for the dominant agg slice (kb<16), 1-term for
    // the ma/input_atom slices (their |contribution| is ~1e-8 of agg's)
    gemm_mma<2><<<gA, 256>>>(agg, ma, input_atom, nullptr, nullptr,
                             fmt + OFF_WLR, h1, nullptr, nullptr, A_N, 3 * H, 48, 16);

    gemm_mma<3><<<gA, 256>>>(h1, nullptr, nullptr, nullptr, nullptr,
                             fmt + OFF_WO, ah, nullptr, b_o, A_N, H, 16, 16);

    scan_kernel<<<1, 1024>>>(sizes);
    pool_kernel<<<M_N, 64>>>(ah, sizes, out);
}

// round 9
// speedup vs baseline: 1.3866x; 1.0078x over previous
#include <cuda_runtime.h>
#include <cstdint>

#define A_N 100000
#define B_N 200000
#define NBN 6
#define FA 133
#define FB 147
#define H 256
#define M_N 5000
#define DEPTH 4

// ---------------- device scratch (no allocations allowed) ----------------
__device__ float g_input_atom[(size_t)A_N * H];
__device__ float g_input_bond[(size_t)B_N * H];
__device__ float g_message_atom[(size_t)A_N * H];
__device__ float g_mb0[(size_t)B_N * H];
__device__ float g_mb1[(size_t)B_N * H];
__device__ float g_agg[(size_t)A_N * H];
__device__ float g_h1[(size_t)A_N * H];
__device__ float g_ah[(size_t)A_N * H];
__device__ int   g_offsets[M_N];

// pre-formatted B weights: per region (ny, kb16) 4096 floats, fragment layout,
// element idx = ((nig*2+ks)*32 + lane)*4 + slot, slots = {bh0, bh1, bl0, bl1}
// region count = 2 * ceil(K/16) per weight
#define OFF_WIA 0         // 18 regions
#define OFF_WIB 73728     // 20
#define OFF_WH  155648    // 3 * 32
#define OFF_WLR 548864    // 96
#define OFF_WO  942080    // 32
#define FMT_TOTAL 1073152
__device__ float g_fmt[FMT_TOTAL];

static inline int cdiv(int a, int b) { return (a + b - 1) / b; }

// ================= helpers =================
__device__ __forceinline__ uint32_t smem_u32(const void* p) {
    uint32_t a;
    asm("{ .reg .u64 t; cvta.to.shared.u64 t, %1; cvt.u32.u64 %0, t; }" : "=r"(a) : "l"(p));
    return a;
}
__device__ __forceinline__ void split_tf32(float x, uint32_t& hi, uint32_t& lo) {
    uint32_t h;
    asm("cvt.rna.tf32.f32 %0, %1;" : "=r"(h) : "f"(x));
    float hf = __uint_as_float(h);
    float r = x - hf;
    uint32_t l;
    asm("cvt.rna.tf32.f32 %0, %1;" : "=r"(l) : "f"(r));
    hi = h; lo = l;
}
__device__ __forceinline__ uint32_t cvt_tf32(float x) {
    uint32_t h;
    asm("cvt.rna.tf32.f32 %0, %1;" : "=r"(h) : "f"(x));
    return h;
}
__device__ __forceinline__ void mma_tf32(float* c, const uint32_t* a, const uint32_t* b) {
    asm volatile(
        "mma.sync.aligned.m16n8k8.row.col.f32.tf32.tf32.f32 "
        "{%0,%1,%2,%3}, {%4,%5,%6,%7}, {%8,%9}, {%0,%1,%2,%3};\n"
        : "+f"(c[0]), "+f"(c[1]), "+f"(c[2]), "+f"(c[3])
        : "r"(a[0]), "r"(a[1]), "r"(a[2]), "r"(a[3]), "r"(b[0]), "r"(b[1]));
}
__device__ __forceinline__ void cp16(uint32_t dst, const void* src) {
    asm volatile("cp.async.cg.shared.global [%0], [%1], 16;" :: "r"(dst), "l"(src));
}

// ================= weight prep: split + fragment layout, region-dispatched ====
// region rb (within a weight) = ny*KB + kb; global region id selects the weight.
// WIA [0,18), WIB [18,38), WH [38,134) (3x32), WLR [134,230), WO [230,262)
__global__ __launch_bounds__(128)
void prep_all(const float* __restrict__ W_ia, const float* __restrict__ W_ib,
              const float* __restrict__ W_h,  const float* __restrict__ W_lr,
              const float* __restrict__ W_o,  int rb_base)
{
    const int rb_g = rb_base + blockIdx.x;
    const float* W; int K, KB; long dstoff; int rb;
    if (rb_g < 18)       { W = W_ia; K = FA;    KB = 9;  dstoff = OFF_WIA; rb = rb_g; }
    else if (rb_g < 38)  { W = W_ib; K = FB;    KB = 10; dstoff = OFF_WIB; rb = rb_g - 18; }
    else if (rb_g < 134) { int d = (rb_g - 38) >> 5;
                           W = W_h + (long)d * H * H; K = H; KB = 16;
                           dstoff = OFF_WH + (long)d * 131072; rb = (rb_g - 38) & 31; }
    else if (rb_g < 230) { W = W_lr; K = 3 * H; KB = 48; dstoff = OFF_WLR; rb = rb_g - 134; }
    else                 { W = W_o;  K = H;     KB = 16; dstoff = OFF_WO;  rb = rb_g - 230; }

    const int ny = rb / KB, kb = rb % KB;
    const int t = threadIdx.x;
    float* dst = g_fmt + dstoff + (long)rb * 4096;
#pragma unroll
    for (int i = 0; i < 32; i++) {
        int idx = i * 128 + t;
        int slot = idx & 3;
        int lane = (idx >> 2) & 31;
        int ks   = (idx >> 7) & 1;
        int nig  = idx >> 8;
        int nloc = nig * 8 + (lane >> 2);
        int kloc = ks * 8 + (slot & 1) * 4 + (lane & 3);
        int kg = kb * 16 + kloc;
        int ng = ny * 128 + nloc;
        float v = (kg < K) ? W[(long)kg * 256 + ng] : 0.f;
        uint32_t hi, lo;
        split_tf32(v, hi, lo);
        dst[idx] = __uint_as_float((slot >> 1) ? lo : hi);
    }
}

// ================= mma.sync tf32 3-split GEMM =================
// C[M,256] = op(A)[M,K] @ B[K,256]; CTA: 128 rows x 128 cols (grid.y = n-half)
// 256 threads = 8 warps, layout 4 (m) x 2 (n): warp tile 32x64.
// Each warp splits only its own 2 m16 A-groups (halves in-loop cvt ALU work
// vs the 2x4 layout). B fragments pre-split in global, loaded via cp.async.
// kb3 = leading k-blocks with the full 3-term split; kb >= kb3 -> 1-term tf32.
// MODE 0: plain A scalar loads (ragged K), relu
// MODE 1: A = ma[b2a[r]] - mbprev[b2revb[r]] (K=256), relu(addp + C)
// MODE 2: A from 3 sources (K=768), plain store
// MODE 3: plain A (K=256), relu(C + bias)
template<int MODE>
__global__ __launch_bounds__(256)
void gemm_mma(const float* __restrict__ Ap, const float* __restrict__ A2,
              const float* __restrict__ A3,
              const int* __restrict__ gi1, const int* __restrict__ gi2,
              const float* __restrict__ fmt,
              float* __restrict__ Cp, const float* __restrict__ addp,
              const float* __restrict__ biasp, int M, int K, int KB, int kb3)
{
    __shared__ float  As[2][2048];   // A fragment layout: ((mig*2+ks)*32+lane)*4+slot
    __shared__ float4 Bs[2][1024];   // B fragment layout: (nig*2+ks)*32+lane -> {bh0,bh1,bl0,bl1}

    const int tid = threadIdx.x;
    const int lane = tid & 31;
    const int wid = tid >> 5;
    const int wm = wid & 3;          // 0..3 (m groups of 32 rows)
    const int wn = wid >> 2;         // 0..1 (n halves of 64 cols)
    const int m0 = blockIdx.x * 128;
    const int n0 = blockIdx.y * 128;

    // staging identity: thread stages row srow, k-half skh (8 k each)
    const int srow = tid >> 1;
    const int skh = tid & 1;
    const int gm_s = min(m0 + srow, M - 1);
    int ia = 0, ir = 0;
    if (MODE == 1) { ia = gi1[gm_s]; ir = gi2[gm_s]; }

    // precomputed STS float-indices for the 8 staged elements
    int sts_idx[8];
    {
        int mig = srow >> 4;
#pragma unroll
        for (int j = 0; j < 8; j++) {
            int lt = ((srow & 7) << 2) | (j & 3);
            int slot = (((j >> 2) & 1) << 1) | ((srow >> 3) & 1);
            sts_idx[j] = ((mig * 2 + skh) * 32 + lt) * 4 + slot;
        }
    }

    float acc[2][8][4];
#pragma unroll
    for (int mi = 0; mi < 2; mi++)
#pragma unroll
        for (int ni = 0; ni < 8; ni++)
#pragma unroll
            for (int q = 0; q < 4; q++) acc[mi][ni][q] = 0.f;

    float areg[8];

    auto loadA = [&](int kb) {
        const int kbase = kb * 16 + skh * 8;
        if (MODE == 0) {
            const float* row = Ap + (long)gm_s * K + kbase;
#pragma unroll
            for (int j = 0; j < 8; j++) areg[j] = (kbase + j < K) ? row[j] : 0.f;
        } else if (MODE == 1) {
            const float* ra = Ap + ((long)ia << 8) + kbase;
            const float* rr = A2 + ((long)ir << 8) + kbase;
            float4 x0 = *(const float4*)ra, x1 = *(const float4*)(ra + 4);
            float4 y0 = *(const float4*)rr, y1 = *(const float4*)(rr + 4);
            areg[0] = x0.x - y0.x; areg[1] = x0.y - y0.y; areg[2] = x0.z - y0.z; areg[3] = x0.w - y0.w;
            areg[4] = x1.x - y1.x; areg[5] = x1.y - y1.y; areg[6] = x1.z - y1.z; areg[7] = x1.w - y1.w;
        } else if (MODE == 2) {
            int which = kb >> 4;
            const float* src = (which == 0) ? Ap : (which == 1) ? A2 : A3;
            const float* ra = src + ((long)gm_s << 8) + (kb & 15) * 16 + skh * 8;
            float4 x0 = *(const float4*)ra, x1 = *(const float4*)(ra + 4);
            areg[0] = x0.x; areg[1] = x0.y; areg[2] = x0.z; areg[3] = x0.w;
            areg[4] = x1.x; areg[5] = x1.y; areg[6] = x1.z; areg[7] = x1.w;
        } else {
            const float* ra = Ap + ((long)gm_s << 8) + kbase;
            float4 x0 = *(const float4*)ra, x1 = *(const float4*)(ra + 4);
            areg[0] = x0.x; areg[1] = x0.y; areg[2] = x0.z; areg[3] = x0.w;
            areg[4] = x1.x; areg[5] = x1.y; areg[6] = x1.z; areg[7] = x1.w;
        }
    };

    auto issueB = [&](int kb, int buf) {
        const float4* src = (const float4*)fmt + (long)(blockIdx.y * KB + kb) * 1024;
        uint32_t dst = smem_u32(&Bs[buf][0]);
#pragma unroll
        for (int i = 0; i < 4; i++) {
            int idx = i * 256 + tid;
            cp16(dst + idx * 16, src + idx);
        }
        asm volatile("cp.async.commit_group;" ::: "memory");
    };

    auto storeA = [&](int buf) {
#pragma unroll
        for (int j = 0; j < 8; j++) As[buf][sts_idx[j]] = areg[j];
    };

    auto compute = [&](int buf, bool full3) {
        const float* a_s = As[buf];
        const float4* b_s = Bs[buf];
#pragma unroll
        for (int ks = 0; ks < 2; ks++) {
            // split this warp's 2 A fragments once per ks
            uint32_t ah[2][4], al[2][4];
#pragma unroll
            for (int mi = 0; mi < 2; mi++) {
                int mig = wm * 2 + mi;
                float4 ra = *(const float4*)(a_s + ((mig * 2 + ks) * 32 + lane) * 4);
                if (full3) {
                    split_tf32(ra.x, ah[mi][0], al[mi][0]);
                    split_tf32(ra.y, ah[mi][1], al[mi][1]);
                    split_tf32(ra.z, ah[mi][2], al[mi][2]);
                    split_tf32(ra.w, ah[mi][3], al[mi][3]);
                } else {
                    ah[mi][0] = cvt_tf32(ra.x); ah[mi][1] = cvt_tf32(ra.y);
                    ah[mi][2] = cvt_tf32(ra.z); ah[mi][3] = cvt_tf32(ra.w);
                }
            }
#pragma unroll
            for (int ni = 0; ni < 8; ni++) {
                int nig = wn * 8 + ni;
                float4 f = b_s[(nig * 2 + ks) * 32 + lane];
                uint32_t bh[2], bl[2];
                bh[0] = __float_as_uint(f.x); bh[1] = __float_as_uint(f.y);
                bl[0] = __float_as_uint(f.z); bl[1] = __float_as_uint(f.w);
#pragma unroll
                for (int mi = 0; mi < 2; mi++) {
                    mma_tf32(acc[mi][ni], ah[mi], bh);
                    if (full3) {
                        mma_tf32(acc[mi][ni], ah[mi], bl);
                        mma_tf32(acc[mi][ni], al[mi], bh);
                    }
                }
            }
        }
    };

    // prologue
    loadA(0);
    issueB(0, 0);
    storeA(0);
    asm volatile("cp.async.wait_group 0;" ::: "memory");
    __syncthreads();

    for (int kb = 0; kb < KB; kb++) {
        const int buf = kb & 1;
        const bool more = (kb + 1 < KB);
        if (more) { loadA(kb + 1); issueB(kb + 1, buf ^ 1); }
        compute(buf, kb < kb3);
        if (more) {
            storeA(buf ^ 1);
            asm volatile("cp.async.wait_group 0;" ::: "memory");
        }
        __syncthreads();
    }

    // epilogue
#pragma unroll
    for (int mi = 0; mi < 2; mi++) {
        int r0 = m0 + wm * 32 + mi * 16 + (lane >> 2);
#pragma unroll
        for (int ni = 0; ni < 8; ni++) {
            int c = n0 + wn * 64 + ni * 8 + (lane & 3) * 2;
#pragma unroll
            for (int half = 0; half < 2; half++) {
                int r = r0 + half * 8;
                if (r >= M) continue;
                float x = acc[mi][ni][half * 2 + 0];
                float y = acc[mi][ni][half * 2 + 1];
                long o = (long)r * 256 + c;
                if (MODE == 1) {
                    float2 t = *(const float2*)(addp + o);
                    x += t.x; y += t.y;
                }
                if (MODE == 3) {
                    float2 t = *(const float2*)(biasp + c);
                    x += t.x; y += t.y;
                }
                if (MODE != 2) { x = fmaxf(x, 0.f); y = fmaxf(y, 0.f); }
                *(float2*)(Cp + o) = make_float2(x, y);
            }
        }
    }
}

// ---------------- sum*max neighbor aggregation ----------------
template<bool ADD>
__global__ __launch_bounds__(256)
void sum_max_kernel(const float* __restrict__ mb, const int* __restrict__ a2b,
                    const float* __restrict__ addsrc, float* __restrict__ outp)
{
    int a = blockIdx.x * 4 + (threadIdx.x >> 6);
    if (a >= A_N) return;
    int h = (threadIdx.x & 63) << 2;
    const int* ab = a2b + (long)a * NBN;
    float4 s = make_float4(0.f, 0.f, 0.f, 0.f);
    float4 mx = make_float4(-1e30f, -1e30f, -1e30f, -1e30f);
#pragma unroll
    for (int j = 0; j < NBN; j++) {
        float4 v = *(const float4*)(mb + (long)ab[j] * H + h);
        s.x += v.x; s.y += v.y; s.z += v.z; s.w += v.w;
        mx.x = fmaxf(mx.x, v.x); mx.y = fmaxf(mx.y, v.y);
        mx.z = fmaxf(mx.z, v.z); mx.w = fmaxf(mx.w, v.w);
    }
    long o = (long)a * H + h;
    float4 r = make_float4(s.x * mx.x, s.y * mx.y, s.z * mx.z, s.w * mx.w);
    if (ADD) {
        float4 c = *(const float4*)(addsrc + o);
        r.x += c.x; r.y += c.y; r.z += c.z; r.w += c.w;
    }
    *(float4*)(outp + o) = r;
}

// ---------------- exclusive scan of molecule sizes ----------------
__global__ void scan_kernel(const int* __restrict__ sizes)
{
    __shared__ int part[1024];
    int t = threadIdx.x;
    const int CH = (M_N + 1023) / 1024;
    int base = t * CH;
    int s = 0;
    for (int i = 0; i < CH; i++) {
        int idx = base + i;
        if (idx < M_N) s += sizes[idx];
    }
    part[t] = s;
    __syncthreads();
    for (int off = 1; off < 1024; off <<= 1) {
        int v = (t >= off) ? part[t - off] : 0;
        __syncthreads();
        part[t] += v;
        __syncthreads();
    }
    int run = (t == 0) ? 0 : part[t - 1];
    for (int i = 0; i < CH; i++) {
        int idx = base + i;
        if (idx < M_N) { g_offsets[idx] = run; run += sizes[idx]; }
    }
}

// ---------------- per-molecule mean pooling ----------------
__global__ __launch_bounds__(64)
void pool_kernel(const float* __restrict__ ah, const int* __restrict__ sizes,
                 float* __restrict__ out)
{
    int m = blockIdx.x;
    int h = threadIdx.x << 2;
    int start = g_offsets[m];
    int n = sizes[m];
    float4 s = make_float4(0.f, 0.f, 0.f, 0.f);
    for (int i = 0; i < n; i++) {
        float4 v = *(const float4*)(ah + (long)(start + i) * H + h);
        s.x += v.x; s.y += v.y; s.z += v.z; s.w += v.w;
    }
    float inv = 1.0f / (float)n;
    *(float4*)(out + (long)m * H + h) = make_float4(s.x * inv, s.y * inv, s.z * inv, s.w * inv);
}

// ---------------- launch ----------------
extern "C" void kernel_launch(void* const* d_in, const int* in_sizes, int n_in,
                              void* d_out, int out_size)
{
    const float* f_atoms = (const float*)d_in[0];
    const float* f_bonds = (const float*)d_in[1];
    const float* W_ia    = (const float*)d_in[2];
    const float* W_ib    = (const float*)d_in[3];
    const float* W_h     = (const float*)d_in[4];
    const float* W_o     = (const float*)d_in[5];
    const float* b_o     = (const float*)d_in[6];
    const float* W_lr    = (const float*)d_in[7];
    const int*   a2b     = (const int*)d_in[8];
    const int*   b2a     = (const int*)d_in[9];
    const int*   b2revb  = (const int*)d_in[10];
    const int*   sizes   = (const int*)d_in[11];
    float* out = (float*)d_out;

    float *input_atom, *input_bond, *ma, *mb0, *mb1, *agg, *h1, *ah, *fmt;
    cudaGetSymbolAddress((void**)&input_atom, g_input_atom);
    cudaGetSymbolAddress((void**)&input_bond, g_input_bond);
    cudaGetSymbolAddress((void**)&ma, g_message_atom);
    cudaGetSymbolAddress((void**)&mb0, g_mb0);
    cudaGetSymbolAddress((void**)&mb1, g_mb1);
    cudaGetSymbolAddress((void**)&agg, g_agg);
    cudaGetSymbolAddress((void**)&h1, g_h1);
    cudaGetSymbolAddress((void**)&ah, g_ah);
    cudaGetSymbolAddress((void**)&fmt, g_fmt);

    // weight prep: 262 regions total, split into exactly 2 launches
    prep_all<<<131, 128>>>(W_ia, W_ib, W_h, W_lr, W_o, 0);
    prep_all<<<131, 128>>>(W_ia, W_ib, W_h, W_lr, W_o, 131);

    dim3 gA(cdiv(A_N, 128), 2), gB(cdiv(B_N, 128), 2);

    // input projections (relu)
    gemm_mma<0><<<gA, 256>>>(f_atoms, nullptr, nullptr, nullptr, nullptr,
                             fmt + OFF_WIA, input_atom, nullptr, nullptr, A_N, FA, 9, 9);
    gemm_mma<0><<<gB, 256>>>(f_bonds, nullptr, nullptr, nullptr, nullptr,
                             fmt + OFF_WIB, input_bond, nullptr, nullptr, B_N, FB, 10, 10);

    // message passing (ping-pong bond buffers)
    const float* mbcur = input_bond;
    for (int d = 0; d < DEPTH - 1; d++) {
        sum_max_kernel<true><<<cdiv(A_N, 4), 256>>>(mbcur, a2b,
                                                    (d == 0) ? input_atom : ma, ma);
        float* mbout = (d % 2 == 0) ? mb0 : mb1;
        gemm_mma<1><<<gB, 256>>>(ma, mbcur, nullptr, b2a, b2revb,
                                 fmt + OFF_WH + (long)d * 131072,
                                 mbout, input_bond, nullptr, B_N, H, 16, 16);
        mbcur = mbout;
    }

    // final aggregation + readout
    sum_max_kernel<false><<<cdiv(A_N, 4), 256>>>(mbcur, a2b, nullptr, agg);

    // W_lr GEMM: 3-term tf32 for the dominant agg slice (kb<16), 1-term for
    // the ma/input_atom slices (their |contribution| is ~1e-8 of agg's)
    gemm_mma<2><<<gA, 256>>>(agg, ma, input_atom, nullptr, nullptr,
                             fmt + OFF_WLR, h1, nullptr, nullptr, A_N, 3 * H, 48, 16);

    gemm_mma<3><<<gA, 256>>>(h1, nullptr, nullptr, nullptr, nullptr,
                             fmt + OFF_WO, ah, nullptr, b_o, A_N, H, 16, 16);

    scan_kernel<<<1, 1024>>>(sizes);
    pool_kernel<<<M_N, 64>>>(ah, sizes, out);
}

// round 10
// speedup vs baseline: 1.3929x; 1.0046x over previous
#include <cuda_runtime.h>
#include <cstdint>

#define A_N 100000
#define B_N 200000
#define NBN 6
#define FA 133
#define FB 147
#define H 256
#define M_N 5000
#define DEPTH 4

// ---------------- device scratch (no allocations allowed) ----------------
__device__ float g_input_atom[(size_t)A_N * H];
__device__ float g_input_bond[(size_t)B_N * H];
__device__ float g_message_atom[(size_t)A_N * H];
__device__ float g_mb0[(size_t)B_N * H];
__device__ float g_mb1[(size_t)B_N * H];
__device__ float g_agg[(size_t)A_N * H];
__device__ float g_h1[(size_t)A_N * H];
__device__ float g_ah[(size_t)A_N * H];
__device__ int   g_offsets[M_N];

// pre-formatted B weights: per region (ny, kb16) 4096 floats, fragment layout,
// element idx = ((nig*2+ks)*32 + lane)*4 + slot, slots = {bh0, bh1, bl0, bl1}
// region count = 2 * ceil(K/16) per weight
#define OFF_WIA 0         // 18 regions
#define OFF_WIB 73728     // 20
#define OFF_WH  155648    // 3 * 32
#define OFF_WLR 548864    // 96
#define OFF_WO  942080    // 32
#define FMT_TOTAL 1073152
__device__ float g_fmt[FMT_TOTAL];

static inline int cdiv(int a, int b) { return (a + b - 1) / b; }

// ================= helpers =================
__device__ __forceinline__ uint32_t smem_u32(const void* p) {
    uint32_t a;
    asm("{ .reg .u64 t; cvta.to.shared.u64 t, %1; cvt.u32.u64 %0, t; }" : "=r"(a) : "l"(p));
    return a;
}
__device__ __forceinline__ void split_tf32(float x, uint32_t& hi, uint32_t& lo) {
    uint32_t h;
    asm("cvt.rna.tf32.f32 %0, %1;" : "=r"(h) : "f"(x));
    float hf = __uint_as_float(h);
    float r = x - hf;
    uint32_t l;
    asm("cvt.rna.tf32.f32 %0, %1;" : "=r"(l) : "f"(r));
    hi = h; lo = l;
}
__device__ __forceinline__ uint32_t cvt_tf32(float x) {
    uint32_t h;
    asm("cvt.rna.tf32.f32 %0, %1;" : "=r"(h) : "f"(x));
    return h;
}
__device__ __forceinline__ void mma_tf32(float* c, const uint32_t* a, const uint32_t* b) {
    asm volatile(
        "mma.sync.aligned.m16n8k8.row.col.f32.tf32.tf32.f32 "
        "{%0,%1,%2,%3}, {%4,%5,%6,%7}, {%8,%9}, {%0,%1,%2,%3};\n"
        : "+f"(c[0]), "+f"(c[1]), "+f"(c[2]), "+f"(c[3])
        : "r"(a[0]), "r"(a[1]), "r"(a[2]), "r"(a[3]), "r"(b[0]), "r"(b[1]));
}
__device__ __forceinline__ void cp16(uint32_t dst, const void* src) {
    asm volatile("cp.async.cg.shared.global [%0], [%1], 16;" :: "r"(dst), "l"(src));
}

// ================= weight prep: split + fragment layout, region-dispatched ====
// region rb (within a weight) = ny*KB + kb; global region id selects the weight.
// WIA [0,18), WIB [18,38), WH [38,134) (3x32), WLR [134,230), WO [230,262)
__global__ __launch_bounds__(128)
void prep_all(const float* __restrict__ W_ia, const float* __restrict__ W_ib,
              const float* __restrict__ W_h,  const float* __restrict__ W_lr,
              const float* __restrict__ W_o,  int rb_base)
{
    const int rb_g = rb_base + blockIdx.x;
    const float* W; int K, KB; long dstoff; int rb;
    if (rb_g < 18)       { W = W_ia; K = FA;    KB = 9;  dstoff = OFF_WIA; rb = rb_g; }
    else if (rb_g < 38)  { W = W_ib; K = FB;    KB = 10; dstoff = OFF_WIB; rb = rb_g - 18; }
    else if (rb_g < 134) { int d = (rb_g - 38) >> 5;
                           W = W_h + (long)d * H * H; K = H; KB = 16;
                           dstoff = OFF_WH + (long)d * 131072; rb = (rb_g - 38) & 31; }
    else if (rb_g < 230) { W = W_lr; K = 3 * H; KB = 48; dstoff = OFF_WLR; rb = rb_g - 134; }
    else                 { W = W_o;  K = H;     KB = 16; dstoff = OFF_WO;  rb = rb_g - 230; }

    const int ny = rb / KB, kb = rb % KB;
    const int t = threadIdx.x;
    float* dst = g_fmt + dstoff + (long)rb * 4096;
#pragma unroll
    for (int i = 0; i < 32; i++) {
        int idx = i * 128 + t;
        int slot = idx & 3;
        int lane = (idx >> 2) & 31;
        int ks   = (idx >> 7) & 1;
        int nig  = idx >> 8;
        int nloc = nig * 8 + (lane >> 2);
        int kloc = ks * 8 + (slot & 1) * 4 + (lane & 3);
        int kg = kb * 16 + kloc;
        int ng = ny * 128 + nloc;
        float v = (kg < K) ? W[(long)kg * 256 + ng] : 0.f;
        uint32_t hi, lo;
        split_tf32(v, hi, lo);
        dst[idx] = __uint_as_float((slot >> 1) ? lo : hi);
    }
}

// ================= mma.sync tf32 3-split GEMM =================
// C[M,256] = op(A)[M,K] @ B[K,256]; CTA: 128 rows x 128 cols (grid.y = n-half)
// 256 threads = 8 warps, layout 4 (m) x 2 (n): warp tile 32x64.
// kb3 = leading k-blocks with the full 3-term split; kb >= kb3 -> 1-term tf32.
// MODE 0: plain A scalar loads (ragged K), relu
// MODE 1: A = ma[b2a[r]] - mbprev[b2revb[r]] (K=256), relu(addp + C)
// MODE 2: A from 3 sources (K=768), plain store
// MODE 3: plain A (K=256), relu(C + bias)
template<int MODE>
__global__ __launch_bounds__(256)
void gemm_mma(const float* __restrict__ Ap, const float* __restrict__ A2,
              const float* __restrict__ A3,
              const int* __restrict__ gi1, const int* __restrict__ gi2,
              const float* __restrict__ fmt,
              float* __restrict__ Cp, const float* __restrict__ addp,
              const float* __restrict__ biasp, int M, int K, int KB, int kb3)
{
    __shared__ float  As[2][2048];   // A fragment layout: ((mig*2+ks)*32+lane)*4+slot
    __shared__ float4 Bs[2][1024];   // B fragment layout: (nig*2+ks)*32+lane -> {bh0,bh1,bl0,bl1}

    const int tid = threadIdx.x;
    const int lane = tid & 31;
    const int wid = tid >> 5;
    const int wm = wid & 3;          // 0..3 (m groups of 32 rows)
    const int wn = wid >> 2;         // 0..1 (n halves of 64 cols)
    const int m0 = blockIdx.x * 128;
    const int n0 = blockIdx.y * 128;

    // staging identity: thread stages row srow, k-half skh (8 k each)
    const int srow = tid >> 1;
    const int skh = tid & 1;
    const int gm_s = min(m0 + srow, M - 1);
    int ia = 0, ir = 0;
    if (MODE == 1) { ia = gi1[gm_s]; ir = gi2[gm_s]; }

    // precomputed STS float-indices for the 8 staged elements
    int sts_idx[8];
    {
        int mig = srow >> 4;
#pragma unroll
        for (int j = 0; j < 8; j++) {
            int lt = ((srow & 7) << 2) | (j & 3);
            int slot = (((j >> 2) & 1) << 1) | ((srow >> 3) & 1);
            sts_idx[j] = ((mig * 2 + skh) * 32 + lt) * 4 + slot;
        }
    }

    float acc[2][8][4];
#pragma unroll
    for (int mi = 0; mi < 2; mi++)
#pragma unroll
        for (int ni = 0; ni < 8; ni++)
#pragma unroll
            for (int q = 0; q < 4; q++) acc[mi][ni][q] = 0.f;

    float areg[8];

    auto loadA = [&](int kb) {
        const int kbase = kb * 16 + skh * 8;
        if (MODE == 0) {
            const float* row = Ap + (long)gm_s * K + kbase;
#pragma unroll
            for (int j = 0; j < 8; j++) areg[j] = (kbase + j < K) ? row[j] : 0.f;
        } else if (MODE == 1) {
            const float* ra = Ap + ((long)ia << 8) + kbase;
            const float* rr = A2 + ((long)ir << 8) + kbase;
            float4 x0 = *(const float4*)ra, x1 = *(const float4*)(ra + 4);
            float4 y0 = *(const float4*)rr, y1 = *(const float4*)(rr + 4);
            areg[0] = x0.x - y0.x; areg[1] = x0.y - y0.y; areg[2] = x0.z - y0.z; areg[3] = x0.w - y0.w;
            areg[4] = x1.x - y1.x; areg[5] = x1.y - y1.y; areg[6] = x1.z - y1.z; areg[7] = x1.w - y1.w;
        } else if (MODE == 2) {
            int which = kb >> 4;
            const float* src = (which == 0) ? Ap : (which == 1) ? A2 : A3;
            const float* ra = src + ((long)gm_s << 8) + (kb & 15) * 16 + skh * 8;
            float4 x0 = *(const float4*)ra, x1 = *(const float4*)(ra + 4);
            areg[0] = x0.x; areg[1] = x0.y; areg[2] = x0.z; areg[3] = x0.w;
            areg[4] = x1.x; areg[5] = x1.y; areg[6] = x1.z; areg[7] = x1.w;
        } else {
            const float* ra = Ap + ((long)gm_s << 8) + kbase;
            float4 x0 = *(const float4*)ra, x1 = *(const float4*)(ra + 4);
            areg[0] = x0.x; areg[1] = x0.y; areg[2] = x0.z; areg[3] = x0.w;
            areg[4] = x1.x; areg[5] = x1.y; areg[6] = x1.z; areg[7] = x1.w;
        }
    };

    auto issueB = [&](int kb, int buf) {
        const float4* src = (const float4*)fmt + (long)(blockIdx.y * KB + kb) * 1024;
        uint32_t dst = smem_u32(&Bs[buf][0]);
#pragma unroll
        for (int i = 0; i < 4; i++) {
            int idx = i * 256 + tid;
            cp16(dst + idx * 16, src + idx);
        }
        asm volatile("cp.async.commit_group;" ::: "memory");
    };

    auto storeA = [&](int buf) {
#pragma unroll
        for (int j = 0; j < 8; j++) As[buf][sts_idx[j]] = areg[j];
    };

    auto compute = [&](int buf, bool full3) {
        const float* a_s = As[buf];
        const float4* b_s = Bs[buf];
#pragma unroll
        for (int ks = 0; ks < 2; ks++) {
            // split this warp's 2 A fragments once per ks
            uint32_t ah[2][4], al[2][4];
#pragma unroll
            for (int mi = 0; mi < 2; mi++) {
                int mig = wm * 2 + mi;
                float4 ra = *(const float4*)(a_s + ((mig * 2 + ks) * 32 + lane) * 4);
                if (full3) {
                    split_tf32(ra.x, ah[mi][0], al[mi][0]);
                    split_tf32(ra.y, ah[mi][1], al[mi][1]);
                    split_tf32(ra.z, ah[mi][2], al[mi][2]);
                    split_tf32(ra.w, ah[mi][3], al[mi][3]);
                } else {
                    ah[mi][0] = cvt_tf32(ra.x); ah[mi][1] = cvt_tf32(ra.y);
                    ah[mi][2] = cvt_tf32(ra.z); ah[mi][3] = cvt_tf32(ra.w);
                }
            }
#pragma unroll
            for (int ni = 0; ni < 8; ni++) {
                int nig = wn * 8 + ni;
                float4 f = b_s[(nig * 2 + ks) * 32 + lane];
                uint32_t bh[2], bl[2];
                bh[0] = __float_as_uint(f.x); bh[1] = __float_as_uint(f.y);
                bl[0] = __float_as_uint(f.z); bl[1] = __float_as_uint(f.w);
#pragma unroll
                for (int mi = 0; mi < 2; mi++) {
                    mma_tf32(acc[mi][ni], ah[mi], bh);
                    if (full3) {
                        mma_tf32(acc[mi][ni], ah[mi], bl);
                        mma_tf32(acc[mi][ni], al[mi], bh);
                    }
                }
            }
        }
    };

    // prologue
    loadA(0);
    issueB(0, 0);
    storeA(0);
    asm volatile("cp.async.wait_group 0;" ::: "memory");
    __syncthreads();

    for (int kb = 0; kb < KB; kb++) {
        const int buf = kb & 1;
        const bool more = (kb + 1 < KB);
        if (more) { loadA(kb + 1); issueB(kb + 1, buf ^ 1); }
        compute(buf, kb < kb3);
        if (more) {
            storeA(buf ^ 1);
            asm volatile("cp.async.wait_group 0;" ::: "memory");
        }
        __syncthreads();
    }

    // epilogue
#pragma unroll
    for (int mi = 0; mi < 2; mi++) {
        int r0 = m0 + wm * 32 + mi * 16 + (lane >> 2);
#pragma unroll
        for (int ni = 0; ni < 8; ni++) {
            int c = n0 + wn * 64 + ni * 8 + (lane & 3) * 2;
#pragma unroll
            for (int half = 0; half < 2; half++) {
                int r = r0 + half * 8;
                if (r >= M) continue;
                float x = acc[mi][ni][half * 2 + 0];
                float y = acc[mi][ni][half * 2 + 1];
                long o = (long)r * 256 + c;
                if (MODE == 1) {
                    float2 t = *(const float2*)(addp + o);
                    x += t.x; y += t.y;
                }
                if (MODE == 3) {
                    float2 t = *(const float2*)(biasp + c);
                    x += t.x; y += t.y;
                }
                if (MODE != 2) { x = fmaxf(x, 0.f); y = fmaxf(y, 0.f); }
                *(float2*)(Cp + o) = make_float2(x, y);
            }
        }
    }
}

// ---------------- sum*max neighbor aggregation ----------------
template<bool ADD>
__global__ __launch_bounds__(256)
void sum_max_kernel(const float* __restrict__ mb, const int* __restrict__ a2b,
                    const float* __restrict__ addsrc, float* __restrict__ outp)
{
    int a = blockIdx.x * 4 + (threadIdx.x >> 6);
    if (a >= A_N) return;
    int h = (threadIdx.x & 63) << 2;
    const int* ab = a2b + (long)a * NBN;
    float4 s = make_float4(0.f, 0.f, 0.f, 0.f);
    float4 mx = make_float4(-1e30f, -1e30f, -1e30f, -1e30f);
#pragma unroll
    for (int j = 0; j < NBN; j++) {
        float4 v = *(const float4*)(mb + (long)ab[j] * H + h);
        s.x += v.x; s.y += v.y; s.z += v.z; s.w += v.w;
        mx.x = fmaxf(mx.x, v.x); mx.y = fmaxf(mx.y, v.y);
        mx.z = fmaxf(mx.z, v.z); mx.w = fmaxf(mx.w, v.w);
    }
    long o = (long)a * H + h;
    float4 r = make_float4(s.x * mx.x, s.y * mx.y, s.z * mx.z, s.w * mx.w);
    if (ADD) {
        float4 c = *(const float4*)(addsrc + o);
        r.x += c.x; r.y += c.y; r.z += c.z; r.w += c.w;
    }
    *(float4*)(outp + o) = r;
}

// ---------------- exclusive scan of molecule sizes ----------------
__global__ void scan_kernel(const int* __restrict__ sizes)
{
    __shared__ int part[1024];
    int t = threadIdx.x;
    const int CH = (M_N + 1023) / 1024;
    int base = t * CH;
    int s = 0;
    for (int i = 0; i < CH; i++) {
        int idx = base + i;
        if (idx < M_N) s += sizes[idx];
    }
    part[t] = s;
    __syncthreads();
    for (int off = 1; off < 1024; off <<= 1) {
        int v = (t >= off) ? part[t - off] : 0;
        __syncthreads();
        part[t] += v;
        __syncthreads();
    }
    int run = (t == 0) ? 0 : part[t - 1];
    for (int i = 0; i < CH; i++) {
        int idx = base + i;
        if (idx < M_N) { g_offsets[idx] = run; run += sizes[idx]; }
    }
}

// ---------------- per-molecule mean pooling ----------------
__global__ __launch_bounds__(64)
void pool_kernel(const float* __restrict__ ah, const int* __restrict__ sizes,
                 float* __restrict__ out)
{
    int m = blockIdx.x;
    int h = threadIdx.x << 2;
    int start = g_offsets[m];
    int n = sizes[m];
    float4 s = make_float4(0.f, 0.f, 0.f, 0.f);
    for (int i = 0; i < n; i++) {
        float4 v = *(const float4*)(ah + (long)(start + i) * H + h);
        s.x += v.x; s.y += v.y; s.z += v.z; s.w += v.w;
    }
    float inv = 1.0f / (float)n;
    *(float4*)(out + (long)m * H + h) = make_float4(s.x * inv, s.y * inv, s.z * inv, s.w * inv);
}

// ---------------- launch ----------------
extern "C" void kernel_launch(void* const* d_in, const int* in_sizes, int n_in,
                              void* d_out, int out_size)
{
    const float* f_atoms = (const float*)d_in[0];
    const float* f_bonds = (const float*)d_in[1];
    const float* W_ia    = (const float*)d_in[2];
    const float* W_ib    = (const float*)d_in[3];
    const float* W_h     = (const float*)d_in[4];
    const float* W_o     = (const float*)d_in[5];
    const float* b_o     = (const float*)d_in[6];
    const float* W_lr    = (const float*)d_in[7];
    const int*   a2b     = (const int*)d_in[8];
    const int*   b2a     = (const int*)d_in[9];
    const int*   b2revb  = (const int*)d_in[10];
    const int*   sizes   = (const int*)d_in[11];
    float* out = (float*)d_out;

    float *input_atom, *input_bond, *ma, *mb0, *mb1, *agg, *h1, *ah, *fmt;
    cudaGetSymbolAddress((void**)&input_atom, g_input_atom);
    cudaGetSymbolAddress((void**)&input_bond, g_input_bond);
    cudaGetSymbolAddress((void**)&ma, g_message_atom);
    cudaGetSymbolAddress((void**)&mb0, g_mb0);
    cudaGetSymbolAddress((void**)&mb1, g_mb1);
    cudaGetSymbolAddress((void**)&agg, g_agg);
    cudaGetSymbolAddress((void**)&h1, g_h1);
    cudaGetSymbolAddress((void**)&ah, g_ah);
    cudaGetSymbolAddress((void**)&fmt, g_fmt);

    // weight prep: 262 regions total, split into exactly 2 launches
    prep_all<<<131, 128>>>(W_ia, W_ib, W_h, W_lr, W_o, 0);
    prep_all<<<131, 128>>>(W_ia, W_ib, W_h, W_lr, W_o, 131);

    dim3 gA(cdiv(A_N, 128), 2), gB(cdiv(B_N, 128), 2);

    // input projections (relu) — full 3-term (errors amplified downstream)
    gemm_mma<0><<<gA, 256>>>(f_atoms, nullptr, nullptr, nullptr, nullptr,
                             fmt + OFF_WIA, input_atom, nullptr, nullptr, A_N, FA, 9, 9);
    gemm_mma<0><<<gB, 256>>>(f_bonds, nullptr, nullptr, nullptr, nullptr,
                             fmt + OFF_WIB, input_bond, nullptr, nullptr, B_N, FB, 10, 10);

    // message passing (ping-pong bond buffers) — full 3-term (recurrence)
    const float* mbcur = input_bond;
    for (int d = 0; d < DEPTH - 1; d++) {
        sum_max_kernel<true><<<cdiv(A_N, 4), 256>>>(mbcur, a2b,
                                                    (d == 0) ? input_atom : ma, ma);
        float* mbout = (d % 2 == 0) ? mb0 : mb1;
        gemm_mma<1><<<gB, 256>>>(ma, mbcur, nullptr, b2a, b2revb,
                                 fmt + OFF_WH + (long)d * 131072,
                                 mbout, input_bond, nullptr, B_N, H, 16, 16);
        mbcur = mbout;
    }

    // final aggregation + readout
    sum_max_kernel<false><<<cdiv(A_N, 4), 256>>>(mbcur, a2b, nullptr, agg);

    // W_lr GEMM: 3-term tf32 for the dominant agg slice (kb<16), 1-term for
    // the ma/input_atom slices (their |contribution| is ~1e-8 of agg's)
    gemm_mma<2><<<gA, 256>>>(agg, ma, input_atom, nullptr, nullptr,
                             fmt + OFF_WLR, h1, nullptr, nullptr, A_N, 3 * H, 48, 16);

    // W_o GEMM: final linear stage — 1-term tf32 (error passes unamplified,
    // adds ~3e-4; saves 2/3 of this kernel's mma work)
    gemm_mma<3><<<gA, 256>>>(h1, nullptr, nullptr, nullptr, nullptr,
                             fmt + OFF_WO, ah, nullptr, b_o, A_N, H, 16, 0);

    scan_kernel<<<1, 1024>>>(sizes);
    pool_kernel<<<M_N, 64>>>(ah, sizes, out);
}